// round 15
// baseline (speedup 1.0000x reference)
#include <cuda_runtime.h>
#include <cstdint>
#include <math.h>

typedef unsigned long long ull;

#define Bv 32
#define Lv 1024
#define Hv 512
#define NGROUP 8
#define CPG 16
#define WS 512

// ---------------- device scratch (no cudaMalloc allowed) ----------------
__device__ float g_pre[(size_t)Lv * Bv * 1536];   // [t][b][0..511]=r, [512..1023]=z, [1024..1535]=c
__device__ float g_h [Bv * Hv];
__device__ float g_rh[Bv * Hv];
__device__ unsigned int g_flag[NGROUP * CPG * 32];   // one flag per CTA, own 128B line

// ---------------- f32x2 helpers ----------------
__device__ __forceinline__ float2 unpack2(ull v) {
    float2 f; asm("mov.b64 {%0, %1}, %2;" : "=f"(f.x), "=f"(f.y) : "l"(v)); return f;
}
__device__ __forceinline__ ull pack2(float a, float b) {
    ull r; asm("mov.b64 %0, {%1, %2};" : "=l"(r) : "f"(a), "f"(b)); return r;
}
__device__ __forceinline__ void ffma2(ull& d, ull a, ull b) {
    asm("fma.rn.f32x2 %0, %1, %2, %0;" : "+l"(d) : "l"(a), "l"(b));
}
__device__ __forceinline__ float fast_sigmoid(float x) {
    x = fminf(fmaxf(x, -30.0f), 30.0f);
    return 1.0f / (1.0f + __expf(-x));
}
__device__ __forceinline__ float fast_tanh(float x) {
    x = fminf(fmaxf(x, -15.0f), 15.0f);
    float e = __expf(2.0f * x);
    return (e - 1.0f) / (e + 1.0f);
}

// ---------------- kernel 1: projection GEMM v2 (fp32 f32x2, issue-optimized) ----------------
// CTA 128m x 128n, BK=16, 256 thr, 8m x 8n per thread.
// A staged transposed [k][m]; B staged duplicated [k][{b,b}].
// Inner iter: 4 LDS.64 (A m-pairs, broadcast) + 4 LDS.128 (B dup) + 32 ffma2.
#define GA_SZ (16 * 128)          // floats per A buffer (8KB)
#define GB_SZ (16 * 128)          // ulls per B buffer (16KB)
#define GEMM_SMEM (2 * (GA_SZ * 4 + GB_SZ * 8))   // 49152 B

__global__ void __launch_bounds__(256) gemm_pre(const float* __restrict__ x,
                                                const float* __restrict__ W_ru,
                                                const float* __restrict__ W_c,
                                                const float* __restrict__ b_ru,
                                                const float* __restrict__ b_c) {
    extern __shared__ char gsm[];
    float* As = (float*)gsm;                        // [2][16][128]
    ull*   Bs = (ull*)(gsm + 2 * GA_SZ * 4);        // [2][16][128] dup pairs

    const int tid = threadIdx.x;
    const int n0 = blockIdx.x * 128;
    const int m0 = blockIdx.y * 128;

    const float* Wsrc = (n0 < 1024) ? (W_ru + (size_t)n0 * 1024 + 512)
                                    : (W_c + (size_t)(n0 - 1024) * 1024 + 512);

    // loaders: lane handles one m (or n) row, 8 k values (2 float4)
    const int lm = tid & 127, lk = (tid >> 7) * 8;
    const float* Ap0 = x + (size_t)(m0 + lm) * 512 + lk;
    const float* Bp0 = Wsrc + (size_t)lm * 1024 + lk;

    // compute mapping: tm = tid>>4 (8 m each), tn = tid&15 (8 n each)
    const int tm = tid >> 4, tn = tid & 15;

    ull acc[4][8];
#pragma unroll
    for (int i = 0; i < 4; i++)
#pragma unroll
        for (int j = 0; j < 8; j++) acc[i][j] = 0ull;

    float4 ra0 = *(const float4*)(Ap0);
    float4 ra1 = *(const float4*)(Ap0 + 4);
    float4 rb0 = *(const float4*)(Bp0);
    float4 rb1 = *(const float4*)(Bp0 + 4);

#define STAGE(buf) do {                                                   \
    float* A_ = As + (buf) * GA_SZ;                                       \
    ull*   B_ = Bs + (buf) * GB_SZ;                                       \
    A_[(lk + 0) * 128 + lm] = ra0.x; A_[(lk + 1) * 128 + lm] = ra0.y;     \
    A_[(lk + 2) * 128 + lm] = ra0.z; A_[(lk + 3) * 128 + lm] = ra0.w;     \
    A_[(lk + 4) * 128 + lm] = ra1.x; A_[(lk + 5) * 128 + lm] = ra1.y;     \
    A_[(lk + 6) * 128 + lm] = ra1.z; A_[(lk + 7) * 128 + lm] = ra1.w;     \
    B_[(lk + 0) * 128 + lm] = pack2(rb0.x, rb0.x);                        \
    B_[(lk + 1) * 128 + lm] = pack2(rb0.y, rb0.y);                        \
    B_[(lk + 2) * 128 + lm] = pack2(rb0.z, rb0.z);                        \
    B_[(lk + 3) * 128 + lm] = pack2(rb0.w, rb0.w);                        \
    B_[(lk + 4) * 128 + lm] = pack2(rb1.x, rb1.x);                        \
    B_[(lk + 5) * 128 + lm] = pack2(rb1.y, rb1.y);                        \
    B_[(lk + 6) * 128 + lm] = pack2(rb1.z, rb1.z);                        \
    B_[(lk + 7) * 128 + lm] = pack2(rb1.w, rb1.w);                        \
} while (0)

    STAGE(0);
    __syncthreads();

    for (int kt = 0; kt < 32; kt++) {
        const int cur = kt & 1;
        if (kt < 31) {
            const float* ap = Ap0 + (kt + 1) * 16;
            ra0 = *(const float4*)(ap);
            ra1 = *(const float4*)(ap + 4);
            const float* bp = Bp0 + (kt + 1) * 16;
            rb0 = *(const float4*)(bp);
            rb1 = *(const float4*)(bp + 4);
        }
        const float* A_ = As + cur * GA_SZ + tm * 8;
        const ull*   B_ = Bs + cur * GB_SZ + tn * 8;
#pragma unroll 4
        for (int kk = 0; kk < 16; kk++) {
            const ull* Ar = (const ull*)(A_ + kk * 128);
            ull a0 = Ar[0], a1 = Ar[1], a2 = Ar[2], a3 = Ar[3];
            const ulonglong2* Br = (const ulonglong2*)(B_ + kk * 128);
            ulonglong2 b01 = Br[0], b23 = Br[1], b45 = Br[2], b67 = Br[3];
            ffma2(acc[0][0], a0, b01.x); ffma2(acc[0][1], a0, b01.y);
            ffma2(acc[0][2], a0, b23.x); ffma2(acc[0][3], a0, b23.y);
            ffma2(acc[0][4], a0, b45.x); ffma2(acc[0][5], a0, b45.y);
            ffma2(acc[0][6], a0, b67.x); ffma2(acc[0][7], a0, b67.y);
            ffma2(acc[1][0], a1, b01.x); ffma2(acc[1][1], a1, b01.y);
            ffma2(acc[1][2], a1, b23.x); ffma2(acc[1][3], a1, b23.y);
            ffma2(acc[1][4], a1, b45.x); ffma2(acc[1][5], a1, b45.y);
            ffma2(acc[1][6], a1, b67.x); ffma2(acc[1][7], a1, b67.y);
            ffma2(acc[2][0], a2, b01.x); ffma2(acc[2][1], a2, b01.y);
            ffma2(acc[2][2], a2, b23.x); ffma2(acc[2][3], a2, b23.y);
            ffma2(acc[2][4], a2, b45.x); ffma2(acc[2][5], a2, b45.y);
            ffma2(acc[2][6], a2, b67.x); ffma2(acc[2][7], a2, b67.y);
            ffma2(acc[3][0], a3, b01.x); ffma2(acc[3][1], a3, b01.y);
            ffma2(acc[3][2], a3, b23.x); ffma2(acc[3][3], a3, b23.y);
            ffma2(acc[3][4], a3, b45.x); ffma2(acc[3][5], a3, b45.y);
            ffma2(acc[3][6], a3, b67.x); ffma2(acc[3][7], a3, b67.y);
        }
        __syncthreads();
        if (kt < 31) {
            STAGE((kt + 1) & 1);
            __syncthreads();
        }
    }

    // epilogue: bias + scatter to g_pre[t][b][col]
    const int coln = n0 + tn * 8;
    const float* bias = (n0 < 1024) ? (b_ru + coln) : (b_c + (coln - 1024));
    float bv[8];
#pragma unroll
    for (int i = 0; i < 8; i++) bv[i] = bias[i];

#pragma unroll
    for (int mp = 0; mp < 4; mp++) {
        float ev[8], ov[8];
#pragma unroll
        for (int n = 0; n < 8; n++) {
            float2 f = unpack2(acc[mp][n]);
            ev[n] = f.x + bv[n];
            ov[n] = f.y + bv[n];
        }
        int me = m0 + tm * 8 + 2 * mp;
        int mo = me + 1;
        float* de = g_pre + ((size_t)(me & 1023) * 32 + (me >> 10)) * 1536 + coln;
        float* dо = g_pre + ((size_t)(mo & 1023) * 32 + (mo >> 10)) * 1536 + coln;
        *(float4*)(de)     = make_float4(ev[0], ev[1], ev[2], ev[3]);
        *(float4*)(de + 4) = make_float4(ev[4], ev[5], ev[6], ev[7]);
        *(float4*)(dо)     = make_float4(ov[0], ov[1], ov[2], ov[3]);
        *(float4*)(dо + 4) = make_float4(ov[4], ov[5], ov[6], ov[7]);
    }
}

// ---------------- group barrier ----------------
__device__ __forceinline__ void bar_signal(int grp, int c, unsigned target) {
    asm volatile("st.release.gpu.u32 [%0], %1;"
                 :: "l"(g_flag + ((size_t)(grp * CPG + c) * 32)), "r"(target) : "memory");
}
__device__ __forceinline__ void bar_poll(int grp, unsigned target) {
    if (threadIdx.x < CPG) {
        const unsigned* fp = g_flag + ((size_t)(grp * CPG + threadIdx.x) * 32);
        unsigned v;
        do {
            asm volatile("ld.acquire.gpu.u32 %0, [%1];" : "=r"(v) : "l"(fp) : "memory");
        } while ((int)(v - target) < 0);
    }
    __syncthreads();
}

// ---------------- scan microkernel (R11 proven) ----------------
__device__ __forceinline__ void mk44(const float* __restrict__ wb,
                                     const float* __restrict__ hb, ull* a) {
#pragma unroll
    for (int i = 0; i < 4; i++) {
        const int off = 64 * i;
        ull w0 = *(const ull*)(wb + off);
        ull w1 = *(const ull*)(wb + WS + off);
        ull w2 = *(const ull*)(wb + 2 * WS + off);
        ull w3 = *(const ull*)(wb + 3 * WS + off);
        ull h0 = *(const ull*)(hb + off);
        ull h1 = *(const ull*)(hb + WS + off);
        ull h2 = *(const ull*)(hb + 2 * WS + off);
        ull h3 = *(const ull*)(hb + 3 * WS + off);
        ffma2(a[0],  w0, h0); ffma2(a[1],  w0, h1); ffma2(a[2],  w0, h2); ffma2(a[3],  w0, h3);
        ffma2(a[4],  w1, h0); ffma2(a[5],  w1, h1); ffma2(a[6],  w1, h2); ffma2(a[7],  w1, h3);
        ffma2(a[8],  w2, h0); ffma2(a[9],  w2, h1); ffma2(a[10], w2, h2); ffma2(a[11], w2, h3);
        ffma2(a[12], w3, h0); ffma2(a[13], w3, h1); ffma2(a[14], w3, h2); ffma2(a[15], w3, h3);
    }
}
__device__ __forceinline__ float reduce16(const ull* a, int l) {
    float vals[16];
#pragma unroll
    for (int v = 0; v < 16; v++) { float2 f = unpack2(a[v]); vals[v] = f.x + f.y; }
#pragma unroll
    for (int i = 0; i < 8; i++) {
        float send = (l & 16) ? vals[i] : vals[i + 8];
        float recv = __shfl_xor_sync(0xffffffffu, send, 16);
        vals[i] = ((l & 16) ? vals[i + 8] : vals[i]) + recv;
    }
#pragma unroll
    for (int i = 0; i < 4; i++) {
        float send = (l & 8) ? vals[i] : vals[i + 4];
        float recv = __shfl_xor_sync(0xffffffffu, send, 8);
        vals[i] = ((l & 8) ? vals[i + 4] : vals[i]) + recv;
    }
#pragma unroll
    for (int i = 0; i < 2; i++) {
        float send = (l & 4) ? vals[i] : vals[i + 2];
        float recv = __shfl_xor_sync(0xffffffffu, send, 4);
        vals[i] = ((l & 4) ? vals[i + 2] : vals[i]) + recv;
    }
    {
        float send = (l & 2) ? vals[0] : vals[1];
        float recv = __shfl_xor_sync(0xffffffffu, send, 2);
        vals[0] = ((l & 2) ? vals[1] : vals[0]) + recv;
    }
    return vals[0] + __shfl_xor_sync(0xffffffffu, vals[0], 1);
}

// ---------------- kernel 2: persistent scan, r/z/cand split (R11 verbatim) ----------------
__global__ void __launch_bounds__(512, 1) scan_kernel(const float* __restrict__ W_ru,
                                                      const float* __restrict__ W_c,
                                                      const float* __restrict__ init_h,
                                                      float* __restrict__ out,
                                                      int has_last) {
    extern __shared__ float sm[];
    float* sWr = sm;
    float* sWz = sWr + 32 * WS;
    float* sWc = sWz + 32 * WS;
    float* sh  = sWc + 32 * WS;
    float* srh = sh + 4 * WS;
    float* redR = srh + 4 * WS;
    float* redZ = redR + 128;
    float* redC = redZ + 128;
    __shared__ unsigned sBase;

    const int tid = threadIdx.x;
    const int w = tid >> 5, l = tid & 31;
    const int rg = w >> 1, kh = w & 1;
    const int grp = blockIdx.x >> 4;
    const int c   = blockIdx.x & 15;

    if (tid == 0) sBase = g_flag[(size_t)(grp * CPG + c) * 32];

    for (int i = tid; i < 32 * 128; i += 512) {
        int r = i >> 7, q = (i & 127) * 4;
        *(float4*)(sWr + r * WS + q) = *(const float4*)(W_ru + (size_t)(c * 32 + r) * 1024 + q);
        *(float4*)(sWz + r * WS + q) = *(const float4*)(W_ru + (size_t)(512 + c * 32 + r) * 1024 + q);
        *(float4*)(sWc + r * WS + q) = *(const float4*)(W_c + (size_t)(c * 32 + r) * 1024 + q);
    }
    {
        int b = tid >> 7, q = (tid & 127) * 4;
        *(float4*)(sh + b * WS + q) = *(const float4*)(init_h + (size_t)(grp * 4 + b) * 512 + q);
    }
    __syncthreads();
    const unsigned base = sBase;

    const int oidx = (l >> 1) & 15;
    const int row_local = rg * 4 + (oidx >> 2);
    const int bat = oidx & 3;
    const int nn  = c * 32 + row_local;
    const int gbo = grp * 4 + bat;
    const bool fin = (kh == 0) && ((l & 1) == 0);
    const int ridx = rg * 16 + oidx;

    const float* wr = sWr + (rg * 4) * WS + kh * 256 + 2 * l;
    const float* wz = sWz + (rg * 4) * WS + kh * 256 + 2 * l;
    const float* wc = sWc + (rg * 4) * WS + kh * 256 + 2 * l;
    const float* hh = sh + kh * 256 + 2 * l;
    const float* rr = srh + kh * 256 + 2 * l;

    float xr = 0.f, xz = 0.f, xc = 0.f;
    if (fin) {
        const float* p = g_pre + (size_t)gbo * 1536;
        xr = __ldg(p + nn); xz = __ldg(p + 512 + nn); xc = __ldg(p + 1024 + nn);
    }

    for (int t = 0; t < Lv; t++) {
        // ---- phase R ----
        ull a[16];
#pragma unroll
        for (int i = 0; i < 16; i++) a[i] = 0ull;
        mk44(wr, hh, a);
        float totR = reduce16(a, l);
        if (kh == 1 && (l & 1) == 0) redR[ridx] = totR;
        __syncthreads();
        if (fin) {
            float gate = fast_sigmoid(totR + redR[ridx] + xr);
            __stcg(&g_rh[(size_t)gbo * 512 + nn], gate * sh[bat * WS + nn]);
        }
        __syncthreads();
        if (tid == 0) bar_signal(grp, c, base + 2u * t + 1u);

        // ---- phase Z (local; hides barrier-1) ----
#pragma unroll
        for (int i = 0; i < 16; i++) a[i] = 0ull;
        mk44(wz, hh, a);
        float totZ = reduce16(a, l);
        if (kh == 1 && (l & 1) == 0) redZ[ridx] = totZ;

        bar_poll(grp, base + 2u * t + 1u);

        // ---- stage rh ----
        {
            int b = tid >> 7, q = (tid & 127) * 4;
            float4 v = __ldcg((const float4*)(g_rh + (size_t)(grp * 4 + b) * 512 + q));
            *(float4*)(srh + b * WS + q) = v;
        }
        float zv = 0.f;
        if (fin) zv = fast_sigmoid(totZ + redZ[ridx] + xz);
        __syncthreads();

        // ---- phase C ----
#pragma unroll
        for (int i = 0; i < 16; i++) a[i] = 0ull;
        mk44(wc, rr, a);
        float totC = reduce16(a, l);
        if (kh == 1 && (l & 1) == 0) redC[ridx] = totC;
        __syncthreads();
        float hnew = 0.f;
        if (fin) {
            float cand = fast_tanh(totC + redC[ridx] + xc);
            float hold = sh[bat * WS + nn];
            hnew = hold + zv * (cand - hold);
            __stcg(&g_h[(size_t)gbo * 512 + nn], hnew);
        }
        __syncthreads();
        if (tid == 0) bar_signal(grp, c, base + 2u * t + 2u);

        if (fin) {
            out[(size_t)gbo * ((size_t)Lv * 512) + (size_t)t * 512 + nn] = hnew;
            if (has_last && t == Lv - 1)
                out[(size_t)Bv * Lv * 512 + (size_t)gbo * 512 + nn] = hnew;
            if (t < Lv - 1) {
                const float* p = g_pre + ((size_t)(t + 1) * 32 + gbo) * 1536;
                xr = __ldg(p + nn); xz = __ldg(p + 512 + nn); xc = __ldg(p + 1024 + nn);
            }
        }

        bar_poll(grp, base + 2u * t + 2u);

        // ---- restage h ----
        if (t < Lv - 1) {
            int b = tid >> 7, q = (tid & 127) * 4;
            float4 v = __ldcg((const float4*)(g_h + (size_t)(grp * 4 + b) * 512 + q));
            *(float4*)(sh + b * WS + q) = v;
            __syncthreads();
        }
    }
}

// ---------------- launch ----------------
extern "C" void kernel_launch(void* const* d_in, const int* in_sizes, int n_in,
                              void* d_out, int out_size) {
    const float* x      = (const float*)d_in[0];
    const float* init_h = (const float*)d_in[1];
    const float* W_ru   = (const float*)d_in[2];
    const float* b_ru   = (const float*)d_in[3];
    const float* W_c    = (const float*)d_in[4];
    const float* b_c    = (const float*)d_in[5];
    float* out = (float*)d_out;

    const int scan_smem = (3 * 32 * WS + 8 * WS + 3 * 128) * 4;  // 214,528 B
    cudaFuncSetAttribute(scan_kernel, cudaFuncAttributeMaxDynamicSharedMemorySize, scan_smem);
    cudaFuncSetAttribute(gemm_pre, cudaFuncAttributeMaxDynamicSharedMemorySize, GEMM_SMEM);

    int has_last = (out_size >= Bv * Lv * Hv + Bv * Hv) ? 1 : 0;

    gemm_pre<<<dim3(12, 256), 256, GEMM_SMEM>>>(x, W_ru, W_c, b_ru, b_c);
    scan_kernel<<<NGROUP * CPG, 512, scan_smem>>>(W_ru, W_c, init_h, out, has_last);
}

// round 16
// speedup vs baseline: 1.2395x; 1.2395x over previous
#include <cuda_runtime.h>
#include <cuda_bf16.h>
#include <cstdint>
#include <math.h>

typedef unsigned long long ull;

#define Bv 32
#define Lv 1024
#define Hv 512
#define NGROUP 8
#define CPG 16
#define WS 512

// ---------------- device scratch (no cudaMalloc allowed) ----------------
__device__ float g_pre[(size_t)Lv * Bv * 1536];   // [t][b][0..511]=r-pre, [512..1023]=z-pre, [1024..1535]=c-pre
__device__ float g_h [Bv * Hv];
__device__ float g_rh[Bv * Hv];
__device__ unsigned int g_flag[NGROUP * CPG * 32];   // one flag per CTA, own 128B line

// bf16 split operands for the HMMA projection GEMM
__device__ __nv_bfloat16 g_Ahi[(size_t)32768 * 512];
__device__ __nv_bfloat16 g_Alo[(size_t)32768 * 512];
__device__ __nv_bfloat16 g_Bhi[1536 * 512];
__device__ __nv_bfloat16 g_Blo[1536 * 512];

// ---------------- f32x2 helpers ----------------
__device__ __forceinline__ float2 unpack2(ull v) {
    float2 f; asm("mov.b64 {%0, %1}, %2;" : "=f"(f.x), "=f"(f.y) : "l"(v)); return f;
}
__device__ __forceinline__ void ffma2(ull& d, ull a, ull b) {
    asm("fma.rn.f32x2 %0, %1, %2, %0;" : "+l"(d) : "l"(a), "l"(b));
}
__device__ __forceinline__ float fast_sigmoid(float x) {
    x = fminf(fmaxf(x, -30.0f), 30.0f);
    return 1.0f / (1.0f + __expf(-x));
}
__device__ __forceinline__ float fast_tanh(float x) {
    x = fminf(fmaxf(x, -15.0f), 15.0f);
    float e = __expf(2.0f * x);
    return (e - 1.0f) / (e + 1.0f);
}
__device__ __forceinline__ unsigned smaddr(const void* p) {
    unsigned r;
    asm("{.reg .u64 t; cvta.to.shared.u64 t, %1; cvt.u32.u64 %0, t;}" : "=r"(r) : "l"(p));
    return r;
}

// pairwise named barrier: the two warps of one row-group (64 threads)
#define BARW(id) asm volatile("bar.sync %0, 64;" :: "r"(id) : "memory")

// ---------------- kernel 0: fp32 -> bf16 hi/lo split ----------------
__device__ __forceinline__ void split1(float v, __nv_bfloat16& h, __nv_bfloat16& l) {
    h = __float2bfloat16(v);
    l = __float2bfloat16(v - __bfloat162float(h));
}
__global__ void __launch_bounds__(256) prep_kernel(const float* __restrict__ x,
                                                   const float* __restrict__ W_ru,
                                                   const float* __restrict__ W_c) {
    size_t i = (size_t)blockIdx.x * 256 + threadIdx.x;   // covers 32768*512/4
    {
        size_t e = i * 4;
        float4 v = *(const float4*)(x + e);
        __nv_bfloat16 h0, l0, h1, l1, h2, l2, h3, l3;
        split1(v.x, h0, l0); split1(v.y, h1, l1); split1(v.z, h2, l2); split1(v.w, h3, l3);
        *(__nv_bfloat162*)(g_Ahi + e)     = __nv_bfloat162(h0, h1);
        *(__nv_bfloat162*)(g_Ahi + e + 2) = __nv_bfloat162(h2, h3);
        *(__nv_bfloat162*)(g_Alo + e)     = __nv_bfloat162(l0, l1);
        *(__nv_bfloat162*)(g_Alo + e + 2) = __nv_bfloat162(l2, l3);
    }
    if (i < (size_t)1536 * 512 / 4) {
        size_t e = i * 4;
        int n = (int)(e >> 9);
        int k = (int)(e & 511);
        const float* src = (n < 1024) ? (W_ru + (size_t)n * 1024 + 512 + k)
                                      : (W_c + (size_t)(n - 1024) * 1024 + 512 + k);
        float4 v = *(const float4*)src;
        __nv_bfloat16 h0, l0, h1, l1, h2, l2, h3, l3;
        split1(v.x, h0, l0); split1(v.y, h1, l1); split1(v.z, h2, l2); split1(v.w, h3, l3);
        *(__nv_bfloat162*)(g_Bhi + e)     = __nv_bfloat162(h0, h1);
        *(__nv_bfloat162*)(g_Bhi + e + 2) = __nv_bfloat162(h2, h3);
        *(__nv_bfloat162*)(g_Blo + e)     = __nv_bfloat162(l0, l1);
        *(__nv_bfloat162*)(g_Blo + e + 2) = __nv_bfloat162(l2, l3);
    }
}

// ---------------- kernel 1: HMMA bf16-split GEMM, cp.async 3-stage pipeline (R14) ----------------
#define ASTR 72                 // bf16 per smem row (144B)
#define ABUF_B (128 * 144)      // 18432 B per A buffer
#define BBUF_B (64 * 144)       // 9216 B per B buffer
#define MMA_SMEM (3 * (ABUF_B + BBUF_B))   // 82944 B

#define LDSM_X4(r0, r1, r2, r3, addr) \
    asm volatile("ldmatrix.sync.aligned.m8n8.x4.shared.b16 {%0,%1,%2,%3}, [%4];" \
        : "=r"(r0), "=r"(r1), "=r"(r2), "=r"(r3) : "r"(addr))

#define MMA_BF16(c, a, b0v, b1v) \
    asm volatile("mma.sync.aligned.m16n8k16.row.col.f32.bf16.bf16.f32 " \
        "{%0,%1,%2,%3}, {%4,%5,%6,%7}, {%8,%9}, {%0,%1,%2,%3};" \
        : "+f"((c)[0]), "+f"((c)[1]), "+f"((c)[2]), "+f"((c)[3]) \
        : "r"((a)[0]), "r"((a)[1]), "r"((a)[2]), "r"((a)[3]), "r"(b0v), "r"(b1v))

#define CP_ASYNC16(sdst, gsrc) \
    asm volatile("cp.async.cg.shared.global [%0], [%1], 16;" :: "r"(sdst), "l"(gsrc))
#define CP_COMMIT() asm volatile("cp.async.commit_group;" ::: "memory")
#define CP_WAIT1()  asm volatile("cp.async.wait_group 1;" ::: "memory")
#define CP_WAIT0()  asm volatile("cp.async.wait_group 0;" ::: "memory")

__global__ void __launch_bounds__(256) mma_pre(const float* __restrict__ b_ru,
                                               const float* __restrict__ b_c) {
    extern __shared__ __nv_bfloat16 dsm[];
    const uint32_t smA_u = smaddr(dsm);
    const uint32_t smB_u = smA_u + 3 * ABUF_B;
    const int tid = threadIdx.x;
    const int n0 = blockIdx.x * 64;
    const int m0 = blockIdx.y * 128;
    const int w = tid >> 5, l = tid & 31;
    const int wm = w & 3, wn = w >> 2;

    float c[2][4][4];
#pragma unroll
    for (int i = 0; i < 2; i++)
#pragma unroll
        for (int j = 0; j < 4; j++)
#pragma unroll
            for (int k = 0; k < 4; k++) c[i][j][k] = 0.0f;

    const __nv_bfloat16* Apass[3] = { g_Ahi + (size_t)m0 * 512, g_Ahi + (size_t)m0 * 512,
                                      g_Alo + (size_t)m0 * 512 };
    const __nv_bfloat16* Bpass[3] = { g_Bhi + (size_t)n0 * 512, g_Blo + (size_t)n0 * 512,
                                      g_Bhi + (size_t)n0 * 512 };

    const int lcc = tid & 7;
    const int arow0 = wm * 32 + (l & 7) + ((l >> 3) & 1) * 8;
    const int ahalf = (l >> 4) & 1;
    const int brow0 = wn * 32 + (l & 7) + ((l >> 4) & 1) * 8;
    const int bhalf = (l >> 3) & 1;

#define STAGE_LOAD(it, buf) do {                                                        \
    int _p = (it) >> 3, _k0 = ((it) & 7) * 64;                                          \
    const __nv_bfloat16* _A = Apass[_p] + _k0;                                          \
    const __nv_bfloat16* _B = Bpass[_p] + _k0;                                          \
    uint32_t _ab = smA_u + (buf) * ABUF_B;                                              \
    uint32_t _bb = smB_u + (buf) * BBUF_B;                                              \
    _Pragma("unroll")                                                                   \
    for (int _i = 0; _i < 4; _i++) {                                                    \
        int _row = (tid + 256 * _i) >> 3;                                               \
        CP_ASYNC16(_ab + (uint32_t)(_row * 144 + ((lcc ^ (_row & 7)) * 16)),            \
                   _A + (size_t)_row * 512 + lcc * 8);                                  \
    }                                                                                   \
    _Pragma("unroll")                                                                   \
    for (int _i = 0; _i < 2; _i++) {                                                    \
        int _row = (tid + 256 * _i) >> 3;                                               \
        CP_ASYNC16(_bb + (uint32_t)(_row * 144 + ((lcc ^ (_row & 7)) * 16)),            \
                   _B + (size_t)_row * 512 + lcc * 8);                                  \
    }                                                                                   \
} while (0)

    STAGE_LOAD(0, 0); CP_COMMIT();
    STAGE_LOAD(1, 1); CP_COMMIT();

    int buf = 0;
    for (int it = 0; it < 24; it++) {
        if (it < 23) { CP_WAIT1(); } else { CP_WAIT0(); }
        __syncthreads();
        if (it + 2 < 24) {
            int nb = buf + 2; if (nb >= 3) nb -= 3;
            STAGE_LOAD(it + 2, nb);
            CP_COMMIT();
        }
        const uint32_t ab = smA_u + buf * ABUF_B;
        const uint32_t bb = smB_u + buf * BBUF_B;
#pragma unroll
        for (int kc = 0; kc < 4; kc++) {
            uint32_t a[2][4], b[2][4];
#pragma unroll
            for (int mf = 0; mf < 2; mf++) {
                int row = arow0 + mf * 16;
                int ch = (kc * 2 + ahalf) ^ (row & 7);
                LDSM_X4(a[mf][0], a[mf][1], a[mf][2], a[mf][3],
                        ab + (uint32_t)(row * 144 + ch * 16));
            }
#pragma unroll
            for (int nb2 = 0; nb2 < 2; nb2++) {
                int row = brow0 + nb2 * 16;
                int ch = (kc * 2 + bhalf) ^ (row & 7);
                LDSM_X4(b[nb2][0], b[nb2][1], b[nb2][2], b[nb2][3],
                        bb + (uint32_t)(row * 144 + ch * 16));
            }
#pragma unroll
            for (int mf = 0; mf < 2; mf++)
#pragma unroll
                for (int nf = 0; nf < 4; nf++)
                    MMA_BF16(c[mf][nf], a[mf], b[nf >> 1][(nf & 1) * 2],
                             b[nf >> 1][(nf & 1) * 2 + 1]);
        }
        if (++buf == 3) buf = 0;
    }

    const int g = l >> 2, tig = l & 3;
#pragma unroll
    for (int mf = 0; mf < 2; mf++) {
#pragma unroll
        for (int nf = 0; nf < 4; nf++) {
            int col = n0 + wn * 32 + nf * 8 + tig * 2;
            float bi0 = (col < 1024) ? b_ru[col] : b_c[col - 1024];
            float bi1 = (col < 1024) ? b_ru[col + 1] : b_c[col - 1023];
            int r0 = m0 + wm * 32 + mf * 16 + g;
            int r1 = r0 + 8;
            float2 v0 = make_float2(c[mf][nf][0] + bi0, c[mf][nf][1] + bi1);
            float2 v1 = make_float2(c[mf][nf][2] + bi0, c[mf][nf][3] + bi1);
            *(float2*)&g_pre[((size_t)(r0 & 1023) * 32 + (r0 >> 10)) * 1536 + col] = v0;
            *(float2*)&g_pre[((size_t)(r1 & 1023) * 32 + (r1 >> 10)) * 1536 + col] = v1;
        }
    }
}

// ---------------- group barrier ----------------
__device__ __forceinline__ void bar_signal(int grp, int c, unsigned target) {
    asm volatile("st.release.gpu.u32 [%0], %1;"
                 :: "l"(g_flag + ((size_t)(grp * CPG + c) * 32)), "r"(target) : "memory");
}
__device__ __forceinline__ void bar_poll(int grp, unsigned target) {
    if (threadIdx.x < CPG) {
        const unsigned* fp = g_flag + ((size_t)(grp * CPG + threadIdx.x) * 32);
        unsigned v;
        do {
            asm volatile("ld.acquire.gpu.u32 %0, [%1];" : "=r"(v) : "l"(fp) : "memory");
        } while ((int)(v - target) < 0);
    }
    __syncthreads();
}

// ---------------- scan microkernel (R11 proven) ----------------
__device__ __forceinline__ void mk44(const float* __restrict__ wb,
                                     const float* __restrict__ hb, ull* a) {
#pragma unroll
    for (int i = 0; i < 4; i++) {
        const int off = 64 * i;
        ull w0 = *(const ull*)(wb + off);
        ull w1 = *(const ull*)(wb + WS + off);
        ull w2 = *(const ull*)(wb + 2 * WS + off);
        ull w3 = *(const ull*)(wb + 3 * WS + off);
        ull h0 = *(const ull*)(hb + off);
        ull h1 = *(const ull*)(hb + WS + off);
        ull h2 = *(const ull*)(hb + 2 * WS + off);
        ull h3 = *(const ull*)(hb + 3 * WS + off);
        ffma2(a[0],  w0, h0); ffma2(a[1],  w0, h1); ffma2(a[2],  w0, h2); ffma2(a[3],  w0, h3);
        ffma2(a[4],  w1, h0); ffma2(a[5],  w1, h1); ffma2(a[6],  w1, h2); ffma2(a[7],  w1, h3);
        ffma2(a[8],  w2, h0); ffma2(a[9],  w2, h1); ffma2(a[10], w2, h2); ffma2(a[11], w2, h3);
        ffma2(a[12], w3, h0); ffma2(a[13], w3, h1); ffma2(a[14], w3, h2); ffma2(a[15], w3, h3);
    }
}
__device__ __forceinline__ float reduce16(const ull* a, int l) {
    float vals[16];
#pragma unroll
    for (int v = 0; v < 16; v++) { float2 f = unpack2(a[v]); vals[v] = f.x + f.y; }
#pragma unroll
    for (int i = 0; i < 8; i++) {
        float send = (l & 16) ? vals[i] : vals[i + 8];
        float recv = __shfl_xor_sync(0xffffffffu, send, 16);
        vals[i] = ((l & 16) ? vals[i + 8] : vals[i]) + recv;
    }
#pragma unroll
    for (int i = 0; i < 4; i++) {
        float send = (l & 8) ? vals[i] : vals[i + 4];
        float recv = __shfl_xor_sync(0xffffffffu, send, 8);
        vals[i] = ((l & 8) ? vals[i + 4] : vals[i]) + recv;
    }
#pragma unroll
    for (int i = 0; i < 2; i++) {
        float send = (l & 4) ? vals[i] : vals[i + 2];
        float recv = __shfl_xor_sync(0xffffffffu, send, 4);
        vals[i] = ((l & 4) ? vals[i + 2] : vals[i]) + recv;
    }
    {
        float send = (l & 2) ? vals[0] : vals[1];
        float recv = __shfl_xor_sync(0xffffffffu, send, 2);
        vals[0] = ((l & 2) ? vals[1] : vals[0]) + recv;
    }
    return vals[0] + __shfl_xor_sync(0xffffffffu, vals[0], 1);
}

// ---------------- kernel 2: persistent scan, r/z/cand split ----------------
__global__ void __launch_bounds__(512, 1) scan_kernel(const float* __restrict__ W_ru,
                                                      const float* __restrict__ W_c,
                                                      const float* __restrict__ init_h,
                                                      float* __restrict__ out,
                                                      int has_last) {
    extern __shared__ float sm[];
    float* sWr = sm;
    float* sWz = sWr + 32 * WS;
    float* sWc = sWz + 32 * WS;
    float* sh  = sWc + 32 * WS;
    float* srh = sh + 4 * WS;
    float* redR = srh + 4 * WS;
    float* redZ = redR + 128;
    float* redC = redZ + 128;
    __shared__ unsigned sBase;

    const int tid = threadIdx.x;
    const int w = tid >> 5, l = tid & 31;
    const int rg = w >> 1, kh = w & 1;
    const int grp = blockIdx.x >> 4;
    const int c   = blockIdx.x & 15;

    if (tid == 0) sBase = g_flag[(size_t)(grp * CPG + c) * 32];

    for (int i = tid; i < 32 * 128; i += 512) {
        int r = i >> 7, q = (i & 127) * 4;
        *(float4*)(sWr + r * WS + q) = *(const float4*)(W_ru + (size_t)(c * 32 + r) * 1024 + q);
        *(float4*)(sWz + r * WS + q) = *(const float4*)(W_ru + (size_t)(512 + c * 32 + r) * 1024 + q);
        *(float4*)(sWc + r * WS + q) = *(const float4*)(W_c + (size_t)(c * 32 + r) * 1024 + q);
    }
    {
        int b = tid >> 7, q = (tid & 127) * 4;
        *(float4*)(sh + b * WS + q) = *(const float4*)(init_h + (size_t)(grp * 4 + b) * 512 + q);
    }
    __syncthreads();
    const unsigned base = sBase;

    const int oidx = (l >> 1) & 15;
    const int row_local = rg * 4 + (oidx >> 2);
    const int bat = oidx & 3;
    const int nn  = c * 32 + row_local;
    const int gbo = grp * 4 + bat;
    const bool fin = (kh == 0) && ((l & 1) == 0);
    const int ridx = rg * 16 + oidx;
    const int barid = 1 + rg;

    const float* wr = sWr + (rg * 4) * WS + kh * 256 + 2 * l;
    const float* wz = sWz + (rg * 4) * WS + kh * 256 + 2 * l;
    const float* wc = sWc + (rg * 4) * WS + kh * 256 + 2 * l;
    const float* hh = sh + kh * 256 + 2 * l;
    const float* rr = srh + kh * 256 + 2 * l;

    float xr = 0.f, xz = 0.f, xc = 0.f;
    if (fin) {
        const float* p = g_pre + (size_t)gbo * 1536;
        xr = __ldg(p + nn); xz = __ldg(p + 512 + nn); xc = __ldg(p + 1024 + nn);
    }

    for (int t = 0; t < Lv; t++) {
        // ---- phase R ----
        ull a[16];
#pragma unroll
        for (int i = 0; i < 16; i++) a[i] = 0ull;
        mk44(wr, hh, a);
        float totR = reduce16(a, l);
        if (kh == 1 && (l & 1) == 0) redR[ridx] = totR;
        BARW(barid);                      // pairwise handoff (only these 2 warps couple)
        if (fin) {
            float gate = fast_sigmoid(totR + redR[ridx] + xr);
            __stcg(&g_rh[(size_t)gbo * 512 + nn], gate * sh[bat * WS + nn]);
        }
        __syncthreads();
        if (tid == 0) bar_signal(grp, c, base + 2u * t + 1u);

        // ---- phase Z (local; hides barrier-1) ----
#pragma unroll
        for (int i = 0; i < 16; i++) a[i] = 0ull;
        mk44(wz, hh, a);
        float totZ = reduce16(a, l);
        if (kh == 1 && (l & 1) == 0) redZ[ridx] = totZ;

        bar_poll(grp, base + 2u * t + 1u);

        // ---- stage rh ----
        {
            int b = tid >> 7, q = (tid & 127) * 4;
            float4 v = __ldcg((const float4*)(g_rh + (size_t)(grp * 4 + b) * 512 + q));
            *(float4*)(srh + b * WS + q) = v;
        }
        float zv = 0.f;
        if (fin) zv = fast_sigmoid(totZ + redZ[ridx] + xz);
        __syncthreads();

        // ---- phase C ----
#pragma unroll
        for (int i = 0; i < 16; i++) a[i] = 0ull;
        mk44(wc, rr, a);
        float totC = reduce16(a, l);
        if (kh == 1 && (l & 1) == 0) redC[ridx] = totC;
        BARW(barid);                      // pairwise handoff
        float hnew = 0.f;
        if (fin) {
            float cand = fast_tanh(totC + redC[ridx] + xc);
            float hold = sh[bat * WS + nn];
            hnew = hold + zv * (cand - hold);
            __stcg(&g_h[(size_t)gbo * 512 + nn], hnew);
        }
        __syncthreads();
        if (tid == 0) bar_signal(grp, c, base + 2u * t + 2u);

        if (fin) {
            out[(size_t)gbo * ((size_t)Lv * 512) + (size_t)t * 512 + nn] = hnew;
            if (has_last && t == Lv - 1)
                out[(size_t)Bv * Lv * 512 + (size_t)gbo * 512 + nn] = hnew;
            if (t < Lv - 1) {
                const float* p = g_pre + ((size_t)(t + 1) * 32 + gbo) * 1536;
                xr = __ldg(p + nn); xz = __ldg(p + 512 + nn); xc = __ldg(p + 1024 + nn);
            }
        }

        bar_poll(grp, base + 2u * t + 2u);

        // ---- restage h ----
        if (t < Lv - 1) {
            int b = tid >> 7, q = (tid & 127) * 4;
            float4 v = __ldcg((const float4*)(g_h + (size_t)(grp * 4 + b) * 512 + q));
            *(float4*)(sh + b * WS + q) = v;
            __syncthreads();
        }
    }
}

// ---------------- launch ----------------
extern "C" void kernel_launch(void* const* d_in, const int* in_sizes, int n_in,
                              void* d_out, int out_size) {
    const float* x      = (const float*)d_in[0];
    const float* init_h = (const float*)d_in[1];
    const float* W_ru   = (const float*)d_in[2];
    const float* b_ru   = (const float*)d_in[3];
    const float* W_c    = (const float*)d_in[4];
    const float* b_c    = (const float*)d_in[5];
    float* out = (float*)d_out;

    const int scan_smem = (3 * 32 * WS + 8 * WS + 3 * 128) * 4;  // 214,528 B
    cudaFuncSetAttribute(scan_kernel, cudaFuncAttributeMaxDynamicSharedMemorySize, scan_smem);
    cudaFuncSetAttribute(mma_pre, cudaFuncAttributeMaxDynamicSharedMemorySize, MMA_SMEM);

    int has_last = (out_size >= Bv * Lv * Hv + Bv * Hv) ? 1 : 0;

    prep_kernel<<<16384, 256>>>(x, W_ru, W_c);
    mma_pre<<<dim3(24, 256), 256, MMA_SMEM>>>(b_ru, b_c);
    scan_kernel<<<NGROUP * CPG, 512, scan_smem>>>(W_ru, W_c, init_h, out, has_last);
}